// round 16
// baseline (speedup 1.0000x reference)
#include <cuda_runtime.h>
#include <cuda_bf16.h>

typedef unsigned long long u64;

#define NBH 1024   // B*H
#define TT  4
#define DK  128
#define DV  256

// ---- packed f32x2 helpers (Blackwell sm_103a) ----
__device__ __forceinline__ u64 pk2(float x, float y){
    u64 r; asm("mov.b64 %0, {%1,%2};" : "=l"(r) : "f"(x), "f"(y)); return r;
}
__device__ __forceinline__ u64 pk1(float x){ return pk2(x, x); }
__device__ __forceinline__ void up2(u64 a, float& x, float& y){
    asm("mov.b64 {%0,%1}, %2;" : "=f"(x), "=f"(y) : "l"(a));
}
__device__ __forceinline__ u64 fma2(u64 a, u64 b, u64 c){
    u64 d; asm("fma.rn.f32x2 %0, %1, %2, %3;" : "=l"(d) : "l"(a), "l"(b), "l"(c)); return d;
}
__device__ __forceinline__ u64 add2(u64 a, u64 b){
    u64 d; asm("add.rn.f32x2 %0, %1, %2;" : "=l"(d) : "l"(a), "l"(b)); return d;
}
__device__ __forceinline__ u64 mul2(u64 a, u64 b){
    u64 d; asm("mul.rn.f32x2 %0, %1, %2;" : "=l"(d) : "l"(a), "l"(b)); return d;
}
__device__ __forceinline__ u64 shflx(u64 x, int m){
    return __shfl_xor_sync(0xFFFFFFFFu, x, m);
}

// R15 (best: 51.7us) with k/q loaded into registers ONCE per pair:
// grams, both sweeps, and the rank-1 updates all reuse the same registers,
// removing ~8 duplicate LDS.128 per thread per pair (L1TEX was the top
// utilized unit at 72%). Verified register-safe in R14 (regs=64, no spill).
// 128-thread CTA = one (b,h) x 1/8 Dv (32 cols).
//   cg = tid&7 (4 cols), rg = tid>>3 (8 rows); warp holds 4 rgs.
// Per pair (t0,t1), both sweeps run against the same S (pair-start):
//   d0  = b0*v0/c0 - b0*(S.k0)
//   m1  = S.k1 + (k0.k1) d0 ;  d1 = b1*v1/c1 - b1*m1
//   out0= c0*(S.q0 + (k0.q0) d0)
//   out1= c1*(S.q1 + (k0.q1) d0 + (k1.q1) d1)
//   S  += k0 d0 + k1 d1 ;  final S_out = c3 * S
__global__ __launch_bounds__(128, 8)
void gdn_step_kernel(const float* __restrict__ q, const float* __restrict__ k,
                     const float* __restrict__ v, const float* __restrict__ g,
                     const float* __restrict__ beta, const float* __restrict__ s0,
                     float* __restrict__ out, float* __restrict__ sout)
{
    const int bh    = blockIdx.x >> 3;
    const int oct   = blockIdx.x & 7;
    const int vbase = oct * 32;
    const int tid   = threadIdx.x;
    const int cg    = tid & 7;     // column group (4 cols)
    const int rg    = tid >> 3;    // row group (8 rows)
    const int wid   = tid >> 5;    // warp id (0..3)
    const int lane  = tid & 31;
    const int k0r   = rg * 8;
    const int v0    = vbase + cg * 4;

    __shared__ __align__(16) float qs[TT * DK];
    __shared__ __align__(16) float ks[TT * DK];
    __shared__ __align__(16) float vs[TT * 32];
    __shared__ float gs[TT], bs[TT];
    __shared__ float4 rA[4][8];      // S.k_t0 partials per warp/cg
    __shared__ float4 rB[4][8];      // S.q_t0
    __shared__ float4 rC[4][8];      // S.k_t1
    __shared__ float4 rD[4][8];      // S.q_t1
    __shared__ float4 rG[4][8];      // grams (kq00, kk01, kq01, kq11)
    __shared__ u64    sumsU[4][2][8];
    __shared__ float4 sG[8];

    // ---- front-batched state load: 8 x LDG.128 streaming, coalesced ----
    const size_t sbase = (size_t)bh * (DK * DV);
    ulonglong2 S[8];
#pragma unroll
    for (int kk = 0; kk < 8; kk++){
        float4 f = __ldcs((const float4*)(s0 + sbase + (size_t)(k0r + kk) * DV + v0));
        S[kk].x = pk2(f.x, f.y);
        S[kk].y = pk2(f.z, f.w);
    }

    // ---- stage q/k/v/g/beta into smem (vectorized: 1 LDG.128 each) ----
    {
        const int qb = bh * (TT * DK);
        float4 qv = __ldg((const float4*)(q + qb + tid * 4));
        float4 kv = __ldg((const float4*)(k + qb + tid * 4));
        *(float4*)&qs[tid * 4] = qv;
        *(float4*)&ks[tid * 4] = kv;
        {
            int t = tid >> 5, j = tid & 31;     // 128 = 4*32 exactly
            vs[tid] = __ldg(v + bh * (TT * DV) + t * DV + vbase + j);
        }
        if (tid < TT)            gs[tid] = g[bh * TT + tid];
        else if (tid < 2 * TT)   bs[tid - TT] = beta[bh * TT + tid - TT];
    }
    __syncthreads();

    float c  = 1.0f;    // cumulative decay
    float ci = 1.0f;    // cumulative inverse decay

#pragma unroll
    for (int p = 0; p < 2; p++){
        const int t0 = 2 * p, t1 = 2 * p + 1;

        // ---- load k/q for this pair ONCE (8 LDS.128), reuse everywhere ----
        float4 kA0 = *(const float4*)&ks[t0 * DK + k0r];
        float4 kB0 = *(const float4*)&ks[t0 * DK + k0r + 4];
        float4 qA0 = *(const float4*)&qs[t0 * DK + k0r];
        float4 qB0 = *(const float4*)&qs[t0 * DK + k0r + 4];
        float4 kA1 = *(const float4*)&ks[t1 * DK + k0r];
        float4 kB1 = *(const float4*)&ks[t1 * DK + k0r + 4];
        float4 qA1 = *(const float4*)&qs[t1 * DK + k0r];
        float4 qB1 = *(const float4*)&qs[t1 * DK + k0r + 4];
        float kf0[8] = {kA0.x,kA0.y,kA0.z,kA0.w,kB0.x,kB0.y,kB0.z,kB0.w};
        float qf0[8] = {qA0.x,qA0.y,qA0.z,qA0.w,qB0.x,qB0.y,qB0.z,qB0.w};
        float kf1[8] = {kA1.x,kA1.y,kA1.z,kA1.w,kB1.x,kB1.y,kB1.z,kB1.w};
        float qf1[8] = {qA1.x,qA1.y,qA1.z,qA1.w,qB1.x,qB1.y,qB1.z,qB1.w};

        // ---- gram partials from registers ----
        float kq00 = 0.f, kk01 = 0.f, kq01 = 0.f, kq11 = 0.f;
#pragma unroll
        for (int i = 0; i < 8; i++){
            kq00 = fmaf(kf0[i], qf0[i], kq00);
            kk01 = fmaf(kf0[i], kf1[i], kk01);
            kq01 = fmaf(kf0[i], qf1[i], kq01);
            kq11 = fmaf(kf1[i], qf1[i], kq11);
        }
#pragma unroll
        for (int m = 8; m <= 16; m <<= 1){
            kq00 += __shfl_xor_sync(0xFFFFFFFFu, kq00, m);
            kk01 += __shfl_xor_sync(0xFFFFFFFFu, kk01, m);
            kq01 += __shfl_xor_sync(0xFFFFFFFFu, kq01, m);
            kq11 += __shfl_xor_sync(0xFFFFFFFFu, kq11, m);
        }

        // ---- sweep A: S.k_t0, S.q_t0 ----
        {
            u64 ax=0, ay=0, ox=0, oy=0;
#pragma unroll
            for (int kk = 0; kk < 8; kk++){
                u64 kt2 = pk1(kf0[kk]), qt2 = pk1(qf0[kk]);
                ax = fma2(S[kk].x, kt2, ax); ay = fma2(S[kk].y, kt2, ay);
                ox = fma2(S[kk].x, qt2, ox); oy = fma2(S[kk].y, qt2, oy);
            }
#pragma unroll
            for (int m = 8; m <= 16; m <<= 1){
                ax = add2(ax, shflx(ax, m)); ay = add2(ay, shflx(ay, m));
                ox = add2(ox, shflx(ox, m)); oy = add2(oy, shflx(oy, m));
            }
            if (lane < 8){
                float4 a, b;
                up2(ax, a.x, a.y); up2(ay, a.z, a.w);
                up2(ox, b.x, b.y); up2(oy, b.z, b.w);
                rA[wid][lane] = a;
                rB[wid][lane] = b;
            }
        }
        // ---- sweep B: S.k_t1, S.q_t1 ----
        {
            u64 ax=0, ay=0, ox=0, oy=0;
#pragma unroll
            for (int kk = 0; kk < 8; kk++){
                u64 kt2 = pk1(kf1[kk]), qt2 = pk1(qf1[kk]);
                ax = fma2(S[kk].x, kt2, ax); ay = fma2(S[kk].y, kt2, ay);
                ox = fma2(S[kk].x, qt2, ox); oy = fma2(S[kk].y, qt2, oy);
            }
#pragma unroll
            for (int m = 8; m <= 16; m <<= 1){
                ax = add2(ax, shflx(ax, m)); ay = add2(ay, shflx(ay, m));
                ox = add2(ox, shflx(ox, m)); oy = add2(oy, shflx(oy, m));
            }
            if (lane < 8){
                float4 a, b;
                up2(ax, a.x, a.y); up2(ay, a.z, a.w);
                up2(ox, b.x, b.y); up2(oy, b.z, b.w);
                rC[wid][lane] = a;
                rD[wid][lane] = b;
                rG[wid][lane] = make_float4(kq00, kk01, kq01, kq11);
            }
        }
        __syncthreads();

        // ---- stage2: cross-warp reduce (96 active threads) ----
        if (tid < 64){
            int arr = tid >> 4;
            int h   = (tid >> 3) & 1;
            int c2  = tid & 7;
            const float4* base = (arr == 0) ? &rA[0][0] :
                                 (arr == 1) ? &rB[0][0] :
                                 (arr == 2) ? &rC[0][0] : &rD[0][0];
            u64 s = 0ull;
#pragma unroll
            for (int w = 0; w < 4; w++)
                s = add2(s, ((const u64*)&base[w * 8 + c2])[h]);
            sumsU[arr][h][c2] = s;
        } else if (tid < 96){
            int gf = (tid >> 3) & 3;
            int c2 = tid & 7;
            float s = 0.0f;
#pragma unroll
            for (int w = 0; w < 4; w++)
                s += ((const float*)&rG[w][c2])[gf];
            ((float*)&sG[c2])[gf] = s;
        }
        __syncthreads();

        // ---- local pair recurrence ----
        u64 a0x = sumsU[0][0][cg], a0y = sumsU[0][1][cg];
        u64 o0x = sumsU[1][0][cg], o0y = sumsU[1][1][cg];
        u64 a1x = sumsU[2][0][cg], a1y = sumsU[2][1][cg];
        u64 o1x = sumsU[3][0][cg], o1y = sumsU[3][1][cg];
        float4 gg = sG[cg];    // (kq00, kk01, kq01, kq11)

        c *= __expf(gs[t0]);  ci *= __expf(-gs[t0]);
        float c0 = c, ci0 = ci;
        c *= __expf(gs[t1]);  ci *= __expf(-gs[t1]);
        float c1 = c, ci1 = ci;

        float b0 = bs[t0], b1 = bs[t1];
        float4 v0f = *(const float4*)&vs[t0 * 32 + cg * 4];
        float4 v1f = *(const float4*)&vs[t1 * 32 + cg * 4];

        u64 nb0 = pk1(-b0), b0c = pk1(b0 * ci0);
        u64 d0x = fma2(a0x, nb0, mul2(pk2(v0f.x, v0f.y), b0c));
        u64 d0y = fma2(a0y, nb0, mul2(pk2(v0f.z, v0f.w), b0c));

        u64 gk = pk1(gg.y);
        u64 m1x = fma2(gk, d0x, a1x);
        u64 m1y = fma2(gk, d0y, a1y);

        u64 nb1 = pk1(-b1), b1c = pk1(b1 * ci1);
        u64 d1x = fma2(m1x, nb1, mul2(pk2(v1f.x, v1f.y), b1c));
        u64 d1y = fma2(m1y, nb1, mul2(pk2(v1f.z, v1f.w), b1c));

        if (rg == 0){
            u64 gq00 = pk1(gg.x), gq01 = pk1(gg.z), gq11 = pk1(gg.w);
            u64 c02 = pk1(c0), c12 = pk1(c1);
            ulonglong2 o0, o1;
            o0.x = mul2(fma2(gq00, d0x, o0x), c02);
            o0.y = mul2(fma2(gq00, d0y, o0y), c02);
            u64 tx = fma2(gq01, d0x, o1x); tx = fma2(gq11, d1x, tx);
            u64 ty = fma2(gq01, d0y, o1y); ty = fma2(gq11, d1y, ty);
            o1.x = mul2(tx, c12);
            o1.y = mul2(ty, c12);
            *(ulonglong2*)(out + (size_t)(bh * TT + t0) * DV + v0) = o0;
            *(ulonglong2*)(out + (size_t)(bh * TT + t1) * DV + v0) = o1;
        }

        // ---- apply both rank-1 updates (k regs still live) ----
#pragma unroll
        for (int kk = 0; kk < 8; kk++){
            u64 k02 = pk1(kf0[kk]), k12 = pk1(kf1[kk]);
            S[kk].x = fma2(k02, d0x, S[kk].x);
            S[kk].y = fma2(k02, d0y, S[kk].y);
            S[kk].x = fma2(k12, d1x, S[kk].x);
            S[kk].y = fma2(k12, d1y, S[kk].y);
        }
    }

    // ---- final state writeback: state = c * S', streaming stores ----
    u64 c2 = pk1(c);
#pragma unroll
    for (int kk = 0; kk < 8; kk++){
        u64 wx = mul2(S[kk].x, c2);
        u64 wy = mul2(S[kk].y, c2);
        float4 f;
        up2(wx, f.x, f.y);
        up2(wy, f.z, f.w);
        __stcs((float4*)(sout + sbase + (size_t)(k0r + kk) * DV + v0), f);
    }
}

extern "C" void kernel_launch(void* const* d_in, const int* in_sizes, int n_in,
                              void* d_out, int out_size)
{
    const float* q    = (const float*)d_in[0];
    const float* k    = (const float*)d_in[1];
    const float* v    = (const float*)d_in[2];
    const float* g    = (const float*)d_in[3];
    const float* beta = (const float*)d_in[4];
    const float* s0   = (const float*)d_in[5];
    float* out  = (float*)d_out;
    float* sout = out + (size_t)NBH * TT * DV;   // state follows the T outputs

    gdn_step_kernel<<<NBH * 8, 128>>>(q, k, v, g, beta, s0, out, sout);
}

// round 17
// speedup vs baseline: 1.4325x; 1.4325x over previous
#include <cuda_runtime.h>
#include <cuda_bf16.h>

typedef unsigned long long u64;

#define NBH 1024   // B*H
#define TT  4
#define DK  128
#define DV  256

// ---- packed f32x2 helpers (Blackwell sm_103a) ----
__device__ __forceinline__ u64 pk2(float x, float y){
    u64 r; asm("mov.b64 %0, {%1,%2};" : "=l"(r) : "f"(x), "f"(y)); return r;
}
__device__ __forceinline__ u64 pk1(float x){ return pk2(x, x); }
__device__ __forceinline__ void up2(u64 a, float& x, float& y){
    asm("mov.b64 {%0,%1}, %2;" : "=f"(x), "=f"(y) : "l"(a));
}
__device__ __forceinline__ u64 fma2(u64 a, u64 b, u64 c){
    u64 d; asm("fma.rn.f32x2 %0, %1, %2, %3;" : "=l"(d) : "l"(a), "l"(b), "l"(c)); return d;
}
__device__ __forceinline__ u64 add2(u64 a, u64 b){
    u64 d; asm("add.rn.f32x2 %0, %1, %2;" : "=l"(d) : "l"(a), "l"(b)); return d;
}
__device__ __forceinline__ u64 mul2(u64 a, u64 b){
    u64 d; asm("mul.rn.f32x2 %0, %1, %2;" : "=l"(d) : "l"(a), "l"(b)); return d;
}
__device__ __forceinline__ u64 shflx(u64 x, int m){
    return __shfl_xor_sync(0xFFFFFFFFu, x, m);
}
__device__ __forceinline__ float dot8(const float* a, const float* b){
    float4 a0 = *(const float4*)a, a1 = *(const float4*)(a + 4);
    float4 b0 = *(const float4*)b, b1 = *(const float4*)(b + 4);
    return a0.x*b0.x + a0.y*b0.y + a0.z*b0.z + a0.w*b0.w
         + a1.x*b1.x + a1.y*b1.y + a1.z*b1.z + a1.w*b1.w;
}

// FINAL (R15, best measured: 51.7us). Pairwise Gram-lite gated delta rule.
// 128-thread CTA = one (b,h) x 1/8 Dv (32 cols).
//   cg = tid&7 (4 cols), rg = tid>>3 (8 rows); warp holds 4 rgs.
// Inputs staged in smem (vectorized LDG.128/STS.128); per-phase LDS.128
// broadcast reloads keep live registers at the 64-reg/occupancy-8 boundary
// (hoisting spills -- measured R16). Warp partials pre-reduced via shuffle
// xor8/xor16; only lanes 0-7 write smem. ONE cross-warp reduction
// (2 barriers) per time-step pair. State streams via __ldcs/__stcs.
// Per pair (t0,t1), both sweeps run against the same S (pair-start):
//   d0  = b0*v0/c0 - b0*(S.k0)
//   m1  = S.k1 + (k0.k1) d0 ;  d1 = b1*v1/c1 - b1*m1
//   out0= c0*(S.q0 + (k0.q0) d0)
//   out1= c1*(S.q1 + (k0.q1) d0 + (k1.q1) d1)
//   S  += k0 d0 + k1 d1 ;  final S_out = c3 * S
__global__ __launch_bounds__(128, 8)
void gdn_step_kernel(const float* __restrict__ q, const float* __restrict__ k,
                     const float* __restrict__ v, const float* __restrict__ g,
                     const float* __restrict__ beta, const float* __restrict__ s0,
                     float* __restrict__ out, float* __restrict__ sout)
{
    const int bh    = blockIdx.x >> 3;
    const int oct   = blockIdx.x & 7;
    const int vbase = oct * 32;
    const int tid   = threadIdx.x;
    const int cg    = tid & 7;     // column group (4 cols)
    const int rg    = tid >> 3;    // row group (8 rows)
    const int wid   = tid >> 5;    // warp id (0..3)
    const int lane  = tid & 31;
    const int k0r   = rg * 8;
    const int v0    = vbase + cg * 4;

    __shared__ __align__(16) float qs[TT * DK];
    __shared__ __align__(16) float ks[TT * DK];
    __shared__ __align__(16) float vs[TT * 32];
    __shared__ float gs[TT], bs[TT];
    __shared__ float4 rA[4][8];      // S.k_t0 partials per warp/cg
    __shared__ float4 rB[4][8];      // S.q_t0
    __shared__ float4 rC[4][8];      // S.k_t1
    __shared__ float4 rD[4][8];      // S.q_t1
    __shared__ float4 rG[4][8];      // grams (kq00, kk01, kq01, kq11)
    __shared__ u64    sumsU[4][2][8];
    __shared__ float4 sG[8];

    // ---- front-batched state load: 8 x LDG.128 streaming, coalesced ----
    const size_t sbase = (size_t)bh * (DK * DV);
    ulonglong2 S[8];
#pragma unroll
    for (int kk = 0; kk < 8; kk++){
        float4 f = __ldcs((const float4*)(s0 + sbase + (size_t)(k0r + kk) * DV + v0));
        S[kk].x = pk2(f.x, f.y);
        S[kk].y = pk2(f.z, f.w);
    }

    // ---- stage q/k/v/g/beta into smem (vectorized: 1 LDG.128 each) ----
    {
        const int qb = bh * (TT * DK);
        float4 qv = __ldg((const float4*)(q + qb + tid * 4));
        float4 kv = __ldg((const float4*)(k + qb + tid * 4));
        *(float4*)&qs[tid * 4] = qv;
        *(float4*)&ks[tid * 4] = kv;
        {
            int t = tid >> 5, j = tid & 31;     // 128 = 4*32 exactly
            vs[tid] = __ldg(v + bh * (TT * DV) + t * DV + vbase + j);
        }
        if (tid < TT)            gs[tid] = g[bh * TT + tid];
        else if (tid < 2 * TT)   bs[tid - TT] = beta[bh * TT + tid - TT];
    }
    __syncthreads();

    float c  = 1.0f;    // cumulative decay
    float ci = 1.0f;    // cumulative inverse decay

#pragma unroll
    for (int p = 0; p < 2; p++){
        const int t0 = 2 * p, t1 = 2 * p + 1;
        const float* k0p = &ks[t0 * DK + k0r];
        const float* k1p = &ks[t1 * DK + k0r];
        const float* q0p = &qs[t0 * DK + k0r];
        const float* q1p = &qs[t1 * DK + k0r];

        // ---- gram partials over this thread's 8 rows (contiguous LDS) ----
        float kq00 = dot8(k0p, q0p);
        float kk01 = dot8(k0p, k1p);
        float kq01 = dot8(k0p, q1p);
        float kq11 = dot8(k1p, q1p);
#pragma unroll
        for (int m = 8; m <= 16; m <<= 1){
            kq00 += __shfl_xor_sync(0xFFFFFFFFu, kq00, m);
            kk01 += __shfl_xor_sync(0xFFFFFFFFu, kk01, m);
            kq01 += __shfl_xor_sync(0xFFFFFFFFu, kq01, m);
            kq11 += __shfl_xor_sync(0xFFFFFFFFu, kq11, m);
        }

        // ---- sweep A: S.k_t0, S.q_t0 ----
        {
            float4 kA = *(const float4*)k0p, kB = *(const float4*)(k0p + 4);
            float4 qA = *(const float4*)q0p, qB = *(const float4*)(q0p + 4);
            float kf[8] = {kA.x,kA.y,kA.z,kA.w,kB.x,kB.y,kB.z,kB.w};
            float qf[8] = {qA.x,qA.y,qA.z,qA.w,qB.x,qB.y,qB.z,qB.w};
            u64 ax=0, ay=0, ox=0, oy=0;
#pragma unroll
            for (int kk = 0; kk < 8; kk++){
                u64 kt2 = pk1(kf[kk]), qt2 = pk1(qf[kk]);
                ax = fma2(S[kk].x, kt2, ax); ay = fma2(S[kk].y, kt2, ay);
                ox = fma2(S[kk].x, qt2, ox); oy = fma2(S[kk].y, qt2, oy);
            }
#pragma unroll
            for (int m = 8; m <= 16; m <<= 1){
                ax = add2(ax, shflx(ax, m)); ay = add2(ay, shflx(ay, m));
                ox = add2(ox, shflx(ox, m)); oy = add2(oy, shflx(oy, m));
            }
            if (lane < 8){
                float4 a, b;
                up2(ax, a.x, a.y); up2(ay, a.z, a.w);
                up2(ox, b.x, b.y); up2(oy, b.z, b.w);
                rA[wid][lane] = a;
                rB[wid][lane] = b;
            }
        }
        // ---- sweep B: S.k_t1, S.q_t1 ----
        {
            float4 kA = *(const float4*)k1p, kB = *(const float4*)(k1p + 4);
            float4 qA = *(const float4*)q1p, qB = *(const float4*)(q1p + 4);
            float kf[8] = {kA.x,kA.y,kA.z,kA.w,kB.x,kB.y,kB.z,kB.w};
            float qf[8] = {qA.x,qA.y,qA.z,qA.w,qB.x,qB.y,qB.z,qB.w};
            u64 ax=0, ay=0, ox=0, oy=0;
#pragma unroll
            for (int kk = 0; kk < 8; kk++){
                u64 kt2 = pk1(kf[kk]), qt2 = pk1(qf[kk]);
                ax = fma2(S[kk].x, kt2, ax); ay = fma2(S[kk].y, kt2, ay);
                ox = fma2(S[kk].x, qt2, ox); oy = fma2(S[kk].y, qt2, oy);
            }
#pragma unroll
            for (int m = 8; m <= 16; m <<= 1){
                ax = add2(ax, shflx(ax, m)); ay = add2(ay, shflx(ay, m));
                ox = add2(ox, shflx(ox, m)); oy = add2(oy, shflx(oy, m));
            }
            if (lane < 8){
                float4 a, b;
                up2(ax, a.x, a.y); up2(ay, a.z, a.w);
                up2(ox, b.x, b.y); up2(oy, b.z, b.w);
                rC[wid][lane] = a;
                rD[wid][lane] = b;
                rG[wid][lane] = make_float4(kq00, kk01, kq01, kq11);
            }
        }
        __syncthreads();

        // ---- stage2: cross-warp reduce (96 active threads) ----
        if (tid < 64){
            int arr = tid >> 4;
            int h   = (tid >> 3) & 1;
            int c2  = tid & 7;
            const float4* base = (arr == 0) ? &rA[0][0] :
                                 (arr == 1) ? &rB[0][0] :
                                 (arr == 2) ? &rC[0][0] : &rD[0][0];
            u64 s = 0ull;
#pragma unroll
            for (int w = 0; w < 4; w++)
                s = add2(s, ((const u64*)&base[w * 8 + c2])[h]);
            sumsU[arr][h][c2] = s;
        } else if (tid < 96){
            int gf = (tid >> 3) & 3;
            int c2 = tid & 7;
            float s = 0.0f;
#pragma unroll
            for (int w = 0; w < 4; w++)
                s += ((const float*)&rG[w][c2])[gf];
            ((float*)&sG[c2])[gf] = s;
        }
        __syncthreads();

        // ---- local pair recurrence ----
        u64 a0x = sumsU[0][0][cg], a0y = sumsU[0][1][cg];
        u64 o0x = sumsU[1][0][cg], o0y = sumsU[1][1][cg];
        u64 a1x = sumsU[2][0][cg], a1y = sumsU[2][1][cg];
        u64 o1x = sumsU[3][0][cg], o1y = sumsU[3][1][cg];
        float4 gg = sG[cg];    // (kq00, kk01, kq01, kq11)

        c *= __expf(gs[t0]);  ci *= __expf(-gs[t0]);
        float c0 = c, ci0 = ci;
        c *= __expf(gs[t1]);  ci *= __expf(-gs[t1]);
        float c1 = c, ci1 = ci;

        float b0 = bs[t0], b1 = bs[t1];
        float4 v0f = *(const float4*)&vs[t0 * 32 + cg * 4];
        float4 v1f = *(const float4*)&vs[t1 * 32 + cg * 4];

        u64 nb0 = pk1(-b0), b0c = pk1(b0 * ci0);
        u64 d0x = fma2(a0x, nb0, mul2(pk2(v0f.x, v0f.y), b0c));
        u64 d0y = fma2(a0y, nb0, mul2(pk2(v0f.z, v0f.w), b0c));

        u64 gk = pk1(gg.y);
        u64 m1x = fma2(gk, d0x, a1x);
        u64 m1y = fma2(gk, d0y, a1y);

        u64 nb1 = pk1(-b1), b1c = pk1(b1 * ci1);
        u64 d1x = fma2(m1x, nb1, mul2(pk2(v1f.x, v1f.y), b1c));
        u64 d1y = fma2(m1y, nb1, mul2(pk2(v1f.z, v1f.w), b1c));

        if (rg == 0){
            u64 gq00 = pk1(gg.x), gq01 = pk1(gg.z), gq11 = pk1(gg.w);
            u64 c02 = pk1(c0), c12 = pk1(c1);
            ulonglong2 o0, o1;
            o0.x = mul2(fma2(gq00, d0x, o0x), c02);
            o0.y = mul2(fma2(gq00, d0y, o0y), c02);
            u64 tx = fma2(gq01, d0x, o1x); tx = fma2(gq11, d1x, tx);
            u64 ty = fma2(gq01, d0y, o1y); ty = fma2(gq11, d1y, ty);
            o1.x = mul2(tx, c12);
            o1.y = mul2(ty, c12);
            *(ulonglong2*)(out + (size_t)(bh * TT + t0) * DV + v0) = o0;
            *(ulonglong2*)(out + (size_t)(bh * TT + t1) * DV + v0) = o1;
        }

        // ---- apply both rank-1 updates ----
        {
            float4 kA0 = *(const float4*)k0p, kB0 = *(const float4*)(k0p + 4);
            float4 kA1 = *(const float4*)k1p, kB1 = *(const float4*)(k1p + 4);
            float kf0[8] = {kA0.x,kA0.y,kA0.z,kA0.w,kB0.x,kB0.y,kB0.z,kB0.w};
            float kf1[8] = {kA1.x,kA1.y,kA1.z,kA1.w,kB1.x,kB1.y,kB1.z,kB1.w};
#pragma unroll
            for (int kk = 0; kk < 8; kk++){
                u64 k02 = pk1(kf0[kk]), k12 = pk1(kf1[kk]);
                S[kk].x = fma2(k02, d0x, S[kk].x);
                S[kk].y = fma2(k02, d0y, S[kk].y);
                S[kk].x = fma2(k12, d1x, S[kk].x);
                S[kk].y = fma2(k12, d1y, S[kk].y);
            }
        }
    }

    // ---- final state writeback: state = c * S', streaming stores ----
    u64 c2 = pk1(c);
#pragma unroll
    for (int kk = 0; kk < 8; kk++){
        u64 wx = mul2(S[kk].x, c2);
        u64 wy = mul2(S[kk].y, c2);
        float4 f;
        up2(wx, f.x, f.y);
        up2(wy, f.z, f.w);
        __stcs((float4*)(sout + sbase + (size_t)(k0r + kk) * DV + v0), f);
    }
}

extern "C" void kernel_launch(void* const* d_in, const int* in_sizes, int n_in,
                              void* d_out, int out_size)
{
    const float* q    = (const float*)d_in[0];
    const float* k    = (const float*)d_in[1];
    const float* v    = (const float*)d_in[2];
    const float* g    = (const float*)d_in[3];
    const float* beta = (const float*)d_in[4];
    const float* s0   = (const float*)d_in[5];
    float* out  = (float*)d_out;
    float* sout = out + (size_t)NBH * TT * DV;   // state follows the T outputs

    gdn_step_kernel<<<NBH * 8, 128>>>(q, k, v, g, beta, s0, out, sout);
}